// round 7
// baseline (speedup 1.0000x reference)
#include <cuda_runtime.h>
#include <cuda_bf16.h>
#include <math.h>

// Problem constants
#define B_   4
#define S_   2048
#define D_   1024
#define H_   16
#define DK_  64
#define NEG_ (-1000000000.0f)
#define SCALE_ (0.125f)   // 1/sqrt(64)

typedef unsigned long long u64;

// Packed fp32x2 FMA (Blackwell sm_103a): 2 IEEE fp32 FMAs per instruction.
__device__ __forceinline__ u64 ffma2(u64 a, u64 b, u64 c) {
    u64 d;
    asm("fma.rn.f32x2 %0, %1, %2, %3;" : "=l"(d) : "l"(a), "l"(b), "l"(c));
    return d;
}
__device__ __forceinline__ u64 pack2(float lo, float hi) {
    u64 d;
    asm("mov.b64 %0, {%1, %2};" : "=l"(d) : "f"(lo), "f"(hi));
    return d;
}
__device__ __forceinline__ float2 unpack2(u64 v) {
    float2 r;
    asm("mov.b64 {%0, %1}, %2;" : "=f"(r.x), "=f"(r.y) : "l"(v));
    return r;
}

// Scratch (allocation-free: __device__ globals), head-major [B, H, S, DK]
__device__ float g_qh[(size_t)B_ * H_ * S_ * DK_];
__device__ float g_kh[(size_t)B_ * H_ * S_ * DK_];
__device__ float g_vh[(size_t)B_ * H_ * S_ * DK_];
__device__ float g_ho[(size_t)B_ * H_ * S_ * DK_];

#define BK 16

// 8x8 micro-kernel over one smem tile. acc[4][8]: 4 M-pairs x 8 N cols.
#define MICRO_KERNEL_88()                                                     \
    _Pragma("unroll")                                                         \
    for (int kk = 0; kk < BK; kk++) {                                         \
        ulonglong2 a0 = *(const ulonglong2*)&As[kk][ty * 8];                  \
        ulonglong2 a1 = *(const ulonglong2*)&As[kk][ty * 8 + 4];              \
        ulonglong2 q0 = *(const ulonglong2*)&Bs2[kk][tx * 8];                 \
        ulonglong2 q1 = *(const ulonglong2*)&Bs2[kk][tx * 8 + 2];             \
        ulonglong2 q2 = *(const ulonglong2*)&Bs2[kk][tx * 8 + 4];             \
        ulonglong2 q3 = *(const ulonglong2*)&Bs2[kk][tx * 8 + 6];             \
        u64 av[4] = {a0.x, a0.y, a1.x, a1.y};                                 \
        u64 bv[8] = {q0.x, q0.y, q1.x, q1.y, q2.x, q2.y, q3.x, q3.y};         \
        _Pragma("unroll")                                                     \
        for (int p = 0; p < 4; p++) {                                         \
            _Pragma("unroll")                                                 \
            for (int j = 0; j < 8; j++)                                       \
                acc[p][j] = ffma2(av[p], bv[j], acc[p][j]);                   \
        }                                                                     \
    }

// Store prefetched regs into smem (A plain, B duplicated-packed).
#define STORE_A8(rga0, rga1)                                                  \
    As[alk + 0][alm] = rga0.x; As[alk + 1][alm] = rga0.y;                     \
    As[alk + 2][alm] = rga0.z; As[alk + 3][alm] = rga0.w;                     \
    As[alk + 4][alm] = rga1.x; As[alk + 5][alm] = rga1.y;                     \
    As[alk + 6][alm] = rga1.z; As[alk + 7][alm] = rga1.w;
#define STORE_B8(rgb0, rgb1)                                                  \
    Bs2[alk + 0][alm] = pack2(rgb0.x, rgb0.x);                                \
    Bs2[alk + 1][alm] = pack2(rgb0.y, rgb0.y);                                \
    Bs2[alk + 2][alm] = pack2(rgb0.z, rgb0.z);                                \
    Bs2[alk + 3][alm] = pack2(rgb0.w, rgb0.w);                                \
    Bs2[alk + 4][alm] = pack2(rgb1.x, rgb1.x);                                \
    Bs2[alk + 5][alm] = pack2(rgb1.y, rgb1.y);                                \
    Bs2[alk + 6][alm] = pack2(rgb1.z, rgb1.z);                                \
    Bs2[alk + 7][alm] = pack2(rgb1.w, rgb1.w);

// Thread map for 128x128 tiles: tx = {b7,b2,b1,b0} (0..15), ty = {b6..b3}.
// Warp = 4 ty x 8 tx  ->  minimal crossbar bytes after broadcast dedup.
#define THREAD_MAP_128()                                                      \
    const int tid = threadIdx.x;                                              \
    const int tx = (tid & 7) | ((tid >> 4) & 8);                              \
    const int ty = (tid >> 3) & 15;

// ---------------------------------------------------------------------------
// Kernel 1: QKV projections. out[b,h,s,d] = x[b,s,:] . w[h*64+d,:] + bias
// tile 128x128, grid (8, 64, 3), 256 threads
// ---------------------------------------------------------------------------
__global__ __launch_bounds__(256, 2)
void proj_qkv_kernel(const float* __restrict__ q, const float* __restrict__ k,
                     const float* __restrict__ v,
                     const float* __restrict__ wq, const float* __restrict__ bq,
                     const float* __restrict__ wk, const float* __restrict__ bk,
                     const float* __restrict__ wv, const float* __restrict__ bv)
{
    const float *X, *W, *bias;
    float* out;
    if (blockIdx.z == 0)      { X = q; W = wq; bias = bq; out = g_qh; }
    else if (blockIdx.z == 1) { X = k; W = wk; bias = bk; out = g_kh; }
    else                      { X = v; W = wv; bias = bv; out = g_vh; }

    __shared__ __align__(16) float As[BK][132];
    __shared__ __align__(16) u64   Bs2[BK][128];

    THREAD_MAP_128();
    const int m0 = blockIdx.y * 128;
    const int n0 = blockIdx.x * 128;

    const int alm = tid >> 1;            // 0..127
    const int alk = (tid & 1) << 3;      // 0 or 8

    const float* aptr = X + (size_t)(m0 + alm) * D_ + alk;
    const float* bptr = W + (size_t)(n0 + alm) * D_ + alk;

    u64 acc[4][8] = {};
    float4 ra0, ra1, rb0, rb1;

    ra0 = *(const float4*)(aptr);     ra1 = *(const float4*)(aptr + 4);
    rb0 = *(const float4*)(bptr);     rb1 = *(const float4*)(bptr + 4);

    for (int k0 = 0; k0 < D_; k0 += BK) {
        STORE_A8(ra0, ra1);
        STORE_B8(rb0, rb1);
        __syncthreads();
        if (k0 + BK < D_) {
            ra0 = *(const float4*)(aptr + k0 + BK);
            ra1 = *(const float4*)(aptr + k0 + BK + 4);
            rb0 = *(const float4*)(bptr + k0 + BK);
            rb1 = *(const float4*)(bptr + k0 + BK + 4);
        }
        MICRO_KERNEL_88();
        __syncthreads();
    }

    const int n = n0 + tx * 8;           // 8-aligned: stays inside one head-64 chunk
    const int h = n >> 6, d = n & 63;
    float4 biaA = *(const float4*)(bias + n);
    float4 biaB = *(const float4*)(bias + n + 4);
    #pragma unroll
    for (int p = 0; p < 4; p++) {
        float2 c[8];
        #pragma unroll
        for (int j = 0; j < 8; j++) c[j] = unpack2(acc[p][j]);
        #pragma unroll
        for (int e = 0; e < 2; e++) {
            int m = m0 + ty * 8 + 2 * p + e;
            int b = m >> 11, s = m & (S_ - 1);
            float* dst = out + ((((size_t)b * H_ + h) * S_ + s) * DK_) + d;
            float v0 = e ? c[0].y : c[0].x, v1 = e ? c[1].y : c[1].x;
            float v2 = e ? c[2].y : c[2].x, v3 = e ? c[3].y : c[3].x;
            float v4 = e ? c[4].y : c[4].x, v5 = e ? c[5].y : c[5].x;
            float v6 = e ? c[6].y : c[6].x, v7 = e ? c[7].y : c[7].x;
            *(float4*)(dst)     = make_float4(v0 + biaA.x, v1 + biaA.y, v2 + biaA.z, v3 + biaA.w);
            *(float4*)(dst + 4) = make_float4(v4 + biaB.x, v5 + biaB.y, v6 + biaB.z, v7 + biaB.w);
        }
    }
}

// ---------------------------------------------------------------------------
// Kernel 2: scores = Q K^T * scale, masked. tile 128x128, grid (16, 16, 64)
// ---------------------------------------------------------------------------
__global__ __launch_bounds__(256, 2)
void scores_kernel(const int* __restrict__ mask, float* __restrict__ attn)
{
    const int z = blockIdx.z;
    const int b = z >> 4;
    const float* Q  = g_qh + (size_t)z * S_ * DK_;
    const float* Km = g_kh + (size_t)z * S_ * DK_;
    const int* mbase = mask + (size_t)b * S_ * S_;
    float* out = attn + (size_t)z * S_ * S_;

    __shared__ __align__(16) float As[BK][132];
    __shared__ __align__(16) u64   Bs2[BK][128];

    THREAD_MAP_128();
    const int m0 = blockIdx.y * 128;
    const int n0 = blockIdx.x * 128;

    const int alm = tid >> 1;
    const int alk = (tid & 1) << 3;

    const float* aptr = Q  + (size_t)(m0 + alm) * DK_ + alk;
    const float* bptr = Km + (size_t)(n0 + alm) * DK_ + alk;

    u64 acc[4][8] = {};
    float4 ra0, ra1, rb0, rb1;

    ra0 = *(const float4*)(aptr);     ra1 = *(const float4*)(aptr + 4);
    rb0 = *(const float4*)(bptr);     rb1 = *(const float4*)(bptr + 4);

    for (int k0 = 0; k0 < DK_; k0 += BK) {
        STORE_A8(ra0, ra1);
        STORE_B8(rb0, rb1);
        __syncthreads();
        if (k0 + BK < DK_) {
            ra0 = *(const float4*)(aptr + k0 + BK);
            ra1 = *(const float4*)(aptr + k0 + BK + 4);
            rb0 = *(const float4*)(bptr + k0 + BK);
            rb1 = *(const float4*)(bptr + k0 + BK + 4);
        }
        MICRO_KERNEL_88();
        __syncthreads();
    }

    const int n = n0 + tx * 8;
    #pragma unroll
    for (int p = 0; p < 4; p++) {
        float2 c[8];
        #pragma unroll
        for (int j = 0; j < 8; j++) c[j] = unpack2(acc[p][j]);
        #pragma unroll
        for (int e = 0; e < 2; e++) {
            int m = m0 + ty * 8 + 2 * p + e;
            int4 mA = *(const int4*)(mbase + (size_t)m * S_ + n);
            int4 mB = *(const int4*)(mbase + (size_t)m * S_ + n + 4);
            float v0 = e ? c[0].y : c[0].x, v1 = e ? c[1].y : c[1].x;
            float v2 = e ? c[2].y : c[2].x, v3 = e ? c[3].y : c[3].x;
            float v4 = e ? c[4].y : c[4].x, v5 = e ? c[5].y : c[5].x;
            float v6 = e ? c[6].y : c[6].x, v7 = e ? c[7].y : c[7].x;
            float4 rA, rB;
            rA.x = (mA.x == 0) ? NEG_ : v0 * SCALE_;
            rA.y = (mA.y == 0) ? NEG_ : v1 * SCALE_;
            rA.z = (mA.z == 0) ? NEG_ : v2 * SCALE_;
            rA.w = (mA.w == 0) ? NEG_ : v3 * SCALE_;
            rB.x = (mB.x == 0) ? NEG_ : v4 * SCALE_;
            rB.y = (mB.y == 0) ? NEG_ : v5 * SCALE_;
            rB.z = (mB.z == 0) ? NEG_ : v6 * SCALE_;
            rB.w = (mB.w == 0) ? NEG_ : v7 * SCALE_;
            *(float4*)(out + (size_t)m * S_ + n)     = rA;
            *(float4*)(out + (size_t)m * S_ + n + 4) = rB;
        }
    }
}

// ---------------------------------------------------------------------------
// Kernel 3: in-place row softmax over 2048 elements. 1 block / row, 256 thr.
// ---------------------------------------------------------------------------
__global__ __launch_bounds__(256)
void softmax_kernel(float* __restrict__ attn)
{
    float* p = attn + (size_t)blockIdx.x * S_;
    const int t = threadIdx.x;
    const int lane = t & 31, warp = t >> 5;
    __shared__ float red[8];

    float4 v0 = *(const float4*)(p + t * 8);
    float4 v1 = *(const float4*)(p + t * 8 + 4);

    float mx = fmaxf(fmaxf(fmaxf(v0.x, v0.y), fmaxf(v0.z, v0.w)),
                     fmaxf(fmaxf(v1.x, v1.y), fmaxf(v1.z, v1.w)));
    #pragma unroll
    for (int off = 16; off > 0; off >>= 1)
        mx = fmaxf(mx, __shfl_xor_sync(0xffffffffu, mx, off));
    if (lane == 0) red[warp] = mx;
    __syncthreads();
    float gmx = red[0];
    #pragma unroll
    for (int w = 1; w < 8; w++) gmx = fmaxf(gmx, red[w]);
    __syncthreads();

    v0.x = __expf(v0.x - gmx); v0.y = __expf(v0.y - gmx);
    v0.z = __expf(v0.z - gmx); v0.w = __expf(v0.w - gmx);
    v1.x = __expf(v1.x - gmx); v1.y = __expf(v1.y - gmx);
    v1.z = __expf(v1.z - gmx); v1.w = __expf(v1.w - gmx);

    float s = (v0.x + v0.y + v0.z + v0.w) + (v1.x + v1.y + v1.z + v1.w);
    #pragma unroll
    for (int off = 16; off > 0; off >>= 1)
        s += __shfl_xor_sync(0xffffffffu, s, off);
    if (lane == 0) red[warp] = s;
    __syncthreads();
    float gs = red[0];
    #pragma unroll
    for (int w = 1; w < 8; w++) gs += red[w];
    const float inv = 1.0f / gs;

    v0.x *= inv; v0.y *= inv; v0.z *= inv; v0.w *= inv;
    v1.x *= inv; v1.y *= inv; v1.z *= inv; v1.w *= inv;
    *(float4*)(p + t * 8)     = v0;
    *(float4*)(p + t * 8 + 4) = v1;
}

// ---------------------------------------------------------------------------
// Kernel 4: PV GEMM. per (b,h): [2048,2048] @ [2048,64] -> [2048,64]
// tile 256x64, grid (1, 8, 64), 256 threads; tx 0..7, ty 0..31
// ---------------------------------------------------------------------------
__global__ __launch_bounds__(256, 2)
void pv_kernel(const float* __restrict__ attn)
{
    const int z = blockIdx.z;
    const float* A = attn + (size_t)z * S_ * S_;
    const float* V = g_vh + (size_t)z * S_ * DK_;
    float* out = g_ho + (size_t)z * S_ * DK_;

    __shared__ __align__(16) float As[BK][260];
    __shared__ __align__(16) u64   Bs2[BK][64];

    const int tid = threadIdx.x;
    const int tx = tid & 7;              // 0..7 (8 cols each)
    const int ty = tid >> 3;             // 0..31 (8 rows each)
    const int m0 = blockIdx.y * 256;

    const int alm = tid >> 1;            // 0..127
    const int alk = (tid & 1) << 3;      // 0 or 8
    const int bkk = tid >> 4;            // 0..15
    const int bn4 = (tid & 15) << 2;     // 0..60

    const float* aptr  = A + (size_t)(m0 + alm) * S_ + alk;
    const float* aptr2 = aptr + (size_t)128 * S_;
    const float* bptr  = V + (size_t)bkk * DK_ + bn4;

    u64 acc[4][8] = {};
    float4 ra0, ra1, rc0, rc1, rb;

    ra0 = *(const float4*)(aptr);      ra1 = *(const float4*)(aptr + 4);
    rc0 = *(const float4*)(aptr2);     rc1 = *(const float4*)(aptr2 + 4);
    rb  = *(const float4*)(bptr);

    for (int k0 = 0; k0 < S_; k0 += BK) {
        STORE_A8(ra0, ra1);
        As[alk + 0][alm + 128] = rc0.x; As[alk + 1][alm + 128] = rc0.y;
        As[alk + 2][alm + 128] = rc0.z; As[alk + 3][alm + 128] = rc0.w;
        As[alk + 4][alm + 128] = rc1.x; As[alk + 5][alm + 128] = rc1.y;
        As[alk + 6][alm + 128] = rc1.z; As[alk + 7][alm + 128] = rc1.w;
        Bs2[bkk][bn4 + 0] = pack2(rb.x, rb.x);
        Bs2[bkk][bn4 + 1] = pack2(rb.y, rb.y);
        Bs2[bkk][bn4 + 2] = pack2(rb.z, rb.z);
        Bs2[bkk][bn4 + 3] = pack2(rb.w, rb.w);
        __syncthreads();
        if (k0 + BK < S_) {
            ra0 = *(const float4*)(aptr  + k0 + BK);
            ra1 = *(const float4*)(aptr  + k0 + BK + 4);
            rc0 = *(const float4*)(aptr2 + k0 + BK);
            rc1 = *(const float4*)(aptr2 + k0 + BK + 4);
            rb  = *(const float4*)(bptr + (size_t)(k0 + BK) * DK_);
        }
        MICRO_KERNEL_88();
        __syncthreads();
    }

    const int n = tx * 8;
    #pragma unroll
    for (int p = 0; p < 4; p++) {
        float2 c[8];
        #pragma unroll
        for (int j = 0; j < 8; j++) c[j] = unpack2(acc[p][j]);
        #pragma unroll
        for (int e = 0; e < 2; e++) {
            int m = m0 + ty * 8 + 2 * p + e;
            float* dst = out + (size_t)m * DK_ + n;
            float v0 = e ? c[0].y : c[0].x, v1 = e ? c[1].y : c[1].x;
            float v2 = e ? c[2].y : c[2].x, v3 = e ? c[3].y : c[3].x;
            float v4 = e ? c[4].y : c[4].x, v5 = e ? c[5].y : c[5].x;
            float v6 = e ? c[6].y : c[6].x, v7 = e ? c[7].y : c[7].x;
            *(float4*)(dst)     = make_float4(v0, v1, v2, v3);
            *(float4*)(dst + 4) = make_float4(v4, v5, v6, v7);
        }
    }
}

// ---------------------------------------------------------------------------
// Kernel 5: output projection. tile 128x128, grid (8, 64)
// combined[b,s,k] = g_ho[b][k/64][s][k%64]
// ---------------------------------------------------------------------------
__global__ __launch_bounds__(256, 2)
void outproj_kernel(const float* __restrict__ wo, const float* __restrict__ bo,
                    float* __restrict__ outp)
{
    __shared__ __align__(16) float As[BK][132];
    __shared__ __align__(16) u64   Bs2[BK][128];

    THREAD_MAP_128();
    const int m0 = blockIdx.y * 128;
    const int n0 = blockIdx.x * 128;

    const int alm = tid >> 1;
    const int alk = (tid & 1) << 3;

    // A row base in head-major scratch: combined[b,s,k] = g_ho[b][k/64][s][k%64]
    const int am = m0 + alm;
    const int ab = am >> 11, as = am & (S_ - 1);
    const float* abase = g_ho + (((size_t)ab * H_) * S_ + as) * DK_;  // + h*S_*DK_ + d
    const float* bptr  = wo + (size_t)(n0 + alm) * D_ + alk;

    u64 acc[4][8] = {};
    float4 ra0, ra1, rb0, rb1;

    {
        int kg = alk;                     // k0 = 0
        int h = kg >> 6, d0 = kg & 63;
        const float* src = abase + (size_t)h * S_ * DK_ + d0;
        ra0 = *(const float4*)(src);  ra1 = *(const float4*)(src + 4);
    }
    rb0 = *(const float4*)(bptr);     rb1 = *(const float4*)(bptr + 4);

    for (int k0 = 0; k0 < D_; k0 += BK) {
        STORE_A8(ra0, ra1);
        STORE_B8(rb0, rb1);
        __syncthreads();
        if (k0 + BK < D_) {
            int kg = k0 + BK + alk;       // 8-aligned; stays in one 64-chunk
            int h = kg >> 6, d0 = kg & 63;
            const float* src = abase + (size_t)h * S_ * DK_ + d0;
            ra0 = *(const float4*)(src);
            ra1 = *(const float4*)(src + 4);
            rb0 = *(const float4*)(bptr + k0 + BK);
            rb1 = *(const float4*)(bptr + k0 + BK + 4);
        }
        MICRO_KERNEL_88();
        __syncthreads();
    }

    const int n = n0 + tx * 8;
    float4 biaA = *(const float4*)(bo + n);
    float4 biaB = *(const float4*)(bo + n + 4);
    #pragma unroll
    for (int p = 0; p < 4; p++) {
        float2 c[8];
        #pragma unroll
        for (int j = 0; j < 8; j++) c[j] = unpack2(acc[p][j]);
        #pragma unroll
        for (int e = 0; e < 2; e++) {
            int m = m0 + ty * 8 + 2 * p + e;
            float v0 = e ? c[0].y : c[0].x, v1 = e ? c[1].y : c[1].x;
            float v2 = e ? c[2].y : c[2].x, v3 = e ? c[3].y : c[3].x;
            float v4 = e ? c[4].y : c[4].x, v5 = e ? c[5].y : c[5].x;
            float v6 = e ? c[6].y : c[6].x, v7 = e ? c[7].y : c[7].x;
            *(float4*)(outp + (size_t)m * D_ + n) =
                make_float4(v0 + biaA.x, v1 + biaA.y, v2 + biaA.z, v3 + biaA.w);
            *(float4*)(outp + (size_t)m * D_ + n + 4) =
                make_float4(v4 + biaB.x, v5 + biaB.y, v6 + biaB.z, v7 + biaB.w);
        }
    }
}

// ---------------------------------------------------------------------------
// kernel_launch — input order: q k v mask wq bq wk bk wv bv wo bo
// output layout: [ output (B*S*D) | attn (B*H*S*S) ]
// ---------------------------------------------------------------------------
extern "C" void kernel_launch(void* const* d_in, const int* in_sizes, int n_in,
                              void* d_out, int out_size)
{
    const float* q    = (const float*)d_in[0];
    const float* k    = (const float*)d_in[1];
    const float* v    = (const float*)d_in[2];
    const int*   mask = (const int*)  d_in[3];
    const float* wq   = (const float*)d_in[4];
    const float* bq   = (const float*)d_in[5];
    const float* wk   = (const float*)d_in[6];
    const float* bk   = (const float*)d_in[7];
    const float* wv   = (const float*)d_in[8];
    const float* bv   = (const float*)d_in[9];
    const float* wo   = (const float*)d_in[10];
    const float* bo   = (const float*)d_in[11];

    float* outp = (float*)d_out;
    float* attn = outp + (size_t)B_ * S_ * D_;

    proj_qkv_kernel<<<dim3(D_ / 128, (B_ * S_) / 128, 3), 256>>>(
        q, k, v, wq, bq, wk, bk, wv, bv);

    scores_kernel<<<dim3(S_ / 128, S_ / 128, B_ * H_), 256>>>(mask, attn);

    softmax_kernel<<<B_ * H_ * S_, 256>>>(attn);

    pv_kernel<<<dim3(1, S_ / 256, B_ * H_), 256>>>(attn);

    outproj_kernel<<<dim3(D_ / 128, (B_ * S_) / 128), 256>>>(wo, bo, outp);
}